// round 2
// baseline (speedup 1.0000x reference)
#include <cuda_runtime.h>
#include <cstdint>

// Problem constants (fixed shapes)
#define NB    4
#define NSEQ  512
#define DIMK  64      // dim
#define NCH   256     // attn hidden
#define TJ    128     // j-tile
#define NT    512     // threads per main block

// -------------------- device scratch (no allocations allowed) --------------------
__device__ float d_M   [DIMK * NCH];          // pos_w2 @ attn_w1          [64,256]
__device__ float d_Wq  [DIMK * NCH];          // wqkv_q @ attn_w1          [64,256]
__device__ float d_Wk  [DIMK * NCH];          // wqkv_k @ attn_w1          [64,256]
__device__ float d_cvec[NCH];                 // attn_b1 + pos_b2 @ attn_w1
__device__ float d_qk1 [NB * NSEQ * NCH];     // x @ Wq + cvec             [2048,256]
__device__ float d_kk1 [NB * NSEQ * NCH];     // x @ Wk                    [2048,256]
__device__ float d_v   [NB * NSEQ * DIMK];    // x @ wqkv_v                [2048,64]

// -------------------- packed f32x2 helpers --------------------
__device__ __forceinline__ unsigned long long splat2(float v) {
    unsigned long long r;
    unsigned u = __float_as_uint(v);
    asm("mov.b64 %0, {%1, %1};" : "=l"(r) : "r"(u));
    return r;
}
__device__ __forceinline__ void fma2(unsigned long long& d, unsigned long long a, unsigned long long b) {
    asm("fma.rn.f32x2 %0, %1, %2, %3;" : "=l"(d) : "l"(a), "l"(b), "l"(d));
}
__device__ __forceinline__ float2 unpack2(unsigned long long v) {
    unsigned lo, hi;
    asm("mov.b64 {%0, %1}, %2;" : "=r"(lo), "=r"(hi) : "l"(v));
    float2 r; r.x = __uint_as_float(lo); r.y = __uint_as_float(hi);
    return r;
}

// -------------------- K0a: fold small weight matrices --------------------
// grid 193 x 256. bid<192: (mat = bid/64, row k = bid%64). bid==192: cvec.
__global__ void prep_mats(const float* __restrict__ w_qkv,
                          const float* __restrict__ pos_w2,
                          const float* __restrict__ pos_b2,
                          const float* __restrict__ attn_w1,
                          const float* __restrict__ attn_b1) {
    int c = threadIdx.x;
    int bid = blockIdx.x;
    if (bid == 192) {
        float acc = attn_b1[c];
        #pragma unroll 8
        for (int d = 0; d < DIMK; d++) acc = fmaf(pos_b2[d], attn_w1[d * NCH + c], acc);
        d_cvec[c] = acc;
        return;
    }
    int m = bid >> 6, k = bid & 63;
    const float* src = (m == 0) ? (pos_w2 + k * 64)
                     : (m == 1) ? (w_qkv + k * 192)
                                : (w_qkv + k * 192 + 64);
    float acc = 0.f;
    #pragma unroll 8
    for (int d = 0; d < DIMK; d++) acc = fmaf(src[d], attn_w1[d * NCH + c], acc);
    float* dst = (m == 0) ? d_M : (m == 1) ? d_Wq : d_Wk;
    dst[k * NCH + c] = acc;
}

// -------------------- K0b: per-row projections qk1', kk1, v --------------------
// grid 128 x 256; each block handles 16 rows of the flattened [2048,64] x.
__global__ __launch_bounds__(256) void proj_kernel(const float* __restrict__ x,
                                                   const float* __restrict__ w_qkv) {
    __shared__ float xs[16][64];
    int c = threadIdx.x;
    int row0 = blockIdx.x * 16;
    for (int idx = c; idx < 16 * 64; idx += 256) xs[idx >> 6][idx & 63] = x[row0 * 64 + idx];
    __syncthreads();

    float accq[16], acck[16];
    #pragma unroll
    for (int r = 0; r < 16; r++) { accq[r] = 0.f; acck[r] = 0.f; }
    for (int k = 0; k < 64; k++) {
        float wq = d_Wq[k * NCH + c];
        float wk = d_Wk[k * NCH + c];
        #pragma unroll
        for (int r = 0; r < 16; r++) {
            float xv = xs[r][k];
            accq[r] = fmaf(xv, wq, accq[r]);
            acck[r] = fmaf(xv, wk, acck[r]);
        }
    }
    float cv = d_cvec[c];
    #pragma unroll
    for (int r = 0; r < 16; r++) {
        d_qk1[(size_t)(row0 + r) * NCH + c] = accq[r] + cv;
        d_kk1[(size_t)(row0 + r) * NCH + c] = acck[r];
    }
    // v projection: 256 threads = 4 row-groups x 64 dims
    int d = c & 63, rg = c >> 6;
    for (int r = rg; r < 16; r += 4) {
        float acc = 0.f;
        #pragma unroll 8
        for (int k = 0; k < 64; k++) acc = fmaf(xs[r][k], w_qkv[k * 192 + 128 + d], acc);
        d_v[(size_t)(row0 + r) * 64 + d] = acc;
    }
}

// -------------------- K1: fused per-row attention --------------------
// grid 2048 (one block per (b,i)), 512 threads, ~135.5 KB dynamic smem.
__global__ __launch_bounds__(NT, 1) void pt_main(const float* __restrict__ pos,
                                                 const float* __restrict__ pos_w1,
                                                 const float* __restrict__ pos_b1,
                                                 const float* __restrict__ pos_w2,
                                                 const float* __restrict__ pos_b2,
                                                 const float* __restrict__ attn_w2,
                                                 float* __restrict__ out) {
    extern __shared__ float sm[];
    float* Ms   = sm;             // 16384   M [64][256]
    float* ps   = Ms + 16384;     // 8320    p tile [128][65] (padded)
    float* vs   = ps + 8320;      // 8192    v tile [128][64]
    float* qs   = vs + 8192;      // 256     qk1'(i,:)
    float* w2s  = qs + 256;       // 256     attn_w2
    float* w1s  = w2s + 256;      // 192     pos_w1 [3][64]
    float* b1s  = w1s + 192;      // 64
    float* pj   = b1s + 64;       // 384     pos_j [3][128]
    float* sims = pj + 384;       // 512
    float* gs   = sims + 512;     // 64
    float* red  = gs + 64;        // 64

    int tid = threadIdx.x;
    int bi  = blockIdx.x;         // b*512 + i
    int b   = bi >> 9;

    // stage block-invariant data
    {
        const float4* src = (const float4*)d_M;
        float4* dst = (float4*)Ms;
        for (int idx = tid; idx < 4096; idx += NT) dst[idx] = src[idx];
    }
    if (tid < 256)      { qs[tid] = d_qk1[(size_t)bi * NCH + tid]; w2s[tid] = attn_w2[tid]; }
    else if (tid < 448) { w1s[tid - 256] = pos_w1[tid - 256]; }
    else                { b1s[tid - 448] = pos_b1[tid - 448]; }
    float px = pos[bi * 3 + 0], py = pos[bi * 3 + 1], pz = pos[bi * 3 + 2];
    __syncthreads();

    int jg = tid >> 4;            // 0..31 : j-group (4 rows each)
    int cg = tid & 15;            // 0..15 : channel group
    int jb = jg << 2;

    // ---------------- PASS 1: sims ----------------
    for (int tile = 0; tile < 4; tile++) {
        int j0 = tile * TJ;
        if (tid < 384) {
            int j = tid & 127, d = tid >> 7;
            pj[d * 128 + j] = pos[((size_t)b * NSEQ + j0 + j) * 3 + d];
        }
        __syncthreads();
        // p tile: relu(rel_pos @ pos_w1 + b1)
        for (int idx = tid; idx < TJ * 64; idx += NT) {
            int j = idx >> 6, k = idx & 63;
            float rx = px - pj[j], ry = py - pj[128 + j], rz = pz - pj[256 + j];
            float v = fmaf(rx, w1s[k], fmaf(ry, w1s[64 + k], fmaf(rz, w1s[128 + k], b1s[k])));
            ps[j * 65 + k] = fmaxf(v, 0.f);
        }
        __syncthreads();

        // GEMM: u[128x256] = p @ M, microtile 4j x 16c (8 f32x2 pairs, stride-32)
        unsigned long long acc[4][8];
        #pragma unroll
        for (int jj = 0; jj < 4; jj++)
            #pragma unroll
            for (int t = 0; t < 8; t++) acc[jj][t] = 0ull;

        const float* psr = ps + jb * 65;
        const float* mc  = Ms + (cg << 1);
        #pragma unroll 4
        for (int k = 0; k < 64; k++) {
            unsigned long long p2[4];
            #pragma unroll
            for (int jj = 0; jj < 4; jj++) p2[jj] = splat2(psr[jj * 65 + k]);
            const unsigned long long* mrow = (const unsigned long long*)(mc + k * NCH);
            #pragma unroll
            for (int t = 0; t < 8; t++) {
                unsigned long long mv = mrow[t * 16]; // float offset 32*t
                #pragma unroll
                for (int jj = 0; jj < 4; jj++) fma2(acc[jj][t], p2[jj], mv);
            }
        }

        // epilogue: u = acc + qk1'_i - kk1_j ; relu ; dot w2
        const float* kk = d_kk1 + ((size_t)(b * NSEQ + j0 + jb)) * NCH;
        #pragma unroll
        for (int jj = 0; jj < 4; jj++) {
            float s = 0.f;
            #pragma unroll
            for (int t = 0; t < 8; t++) {
                int c = (cg << 1) + (t << 5);
                float2 kv = *(const float2*)(kk + jj * NCH + c);
                float2 qv = *(const float2*)(qs + c);
                float2 wv = *(const float2*)(w2s + c);
                float2 a  = unpack2(acc[jj][t]);
                float u0 = fmaxf(a.x + qv.x - kv.x, 0.f);
                float u1 = fmaxf(a.y + qv.y - kv.y, 0.f);
                s = fmaf(u0, wv.x, fmaf(u1, wv.y, s));
            }
            s += __shfl_down_sync(0xffffffffu, s, 8, 16);
            s += __shfl_down_sync(0xffffffffu, s, 4, 16);
            s += __shfl_down_sync(0xffffffffu, s, 2, 16);
            s += __shfl_down_sync(0xffffffffu, s, 1, 16);
            if (cg == 0) sims[j0 + jb + jj] = s;
        }
        __syncthreads();
    }

    // ---------------- softmax over 512 sims ----------------
    {
        float s = sims[tid];
        float m = s;
        #pragma unroll
        for (int off = 16; off; off >>= 1) m = fmaxf(m, __shfl_xor_sync(0xffffffffu, m, off));
        if ((tid & 31) == 0) red[tid >> 5] = m;
        __syncthreads();
        if (tid < 32) {
            float v = (tid < 16) ? red[tid] : -3.4e38f;
            #pragma unroll
            for (int off = 8; off; off >>= 1) v = fmaxf(v, __shfl_xor_sync(0xffffffffu, v, off));
            if (tid == 0) red[32] = v;
        }
        __syncthreads();
        float e = __expf(s - red[32]);
        float t = e;
        #pragma unroll
        for (int off = 16; off; off >>= 1) t += __shfl_xor_sync(0xffffffffu, t, off);
        if ((tid & 31) == 0) red[tid >> 5] = t;
        __syncthreads();
        if (tid < 32) {
            float v = (tid < 16) ? red[tid] : 0.f;
            #pragma unroll
            for (int off = 8; off; off >>= 1) v += __shfl_xor_sync(0xffffffffu, v, off);
            if (tid == 0) red[33] = v;
        }
        __syncthreads();
        sims[tid] = e / red[33];
        __syncthreads();
    }

    // ---------------- PASS 2: g = a@p (recompute p), r = a@v ----------------
    float gacc = 0.f, racc = 0.f;
    for (int tile = 0; tile < 4; tile++) {
        int j0 = tile * TJ;
        if (tid < 384) {
            int j = tid & 127, d = tid >> 7;
            pj[d * 128 + j] = pos[((size_t)b * NSEQ + j0 + j) * 3 + d];
        }
        __syncthreads();
        for (int idx = tid; idx < TJ * 64; idx += NT) {
            int j = idx >> 6, k = idx & 63;
            float rx = px - pj[j], ry = py - pj[128 + j], rz = pz - pj[256 + j];
            float v = fmaf(rx, w1s[k], fmaf(ry, w1s[64 + k], fmaf(rz, w1s[128 + k], b1s[k])));
            ps[j * 65 + k] = fmaxf(v, 0.f);
        }
        {
            const float4* src = (const float4*)(d_v + ((size_t)(b * NSEQ + j0)) * 64);
            float4* dst = (float4*)vs;
            for (int idx = tid; idx < TJ * 16; idx += NT) dst[idx] = src[idx];
        }
        __syncthreads();
        if (tid < 64) {
            int k = tid;
            #pragma unroll 8
            for (int j = 0; j < TJ; j++) gacc = fmaf(sims[j0 + j], ps[j * 65 + k], gacc);
        } else if (tid < 128) {
            int d = tid - 64;
            #pragma unroll 8
            for (int j = 0; j < TJ; j++) racc = fmaf(sims[j0 + j], vs[j * 64 + d], racc);
        }
        __syncthreads();
    }

    if (tid < 64) gs[tid] = gacc;
    __syncthreads();
    if (tid >= 64 && tid < 128) {
        int d = tid - 64;
        float o = racc + pos_b2[d];
        #pragma unroll 8
        for (int k = 0; k < 64; k++) o = fmaf(gs[k], pos_w2[k * 64 + d], o);
        out[(size_t)bi * 64 + d] = o;
    }
}

// -------------------- launch --------------------
static const int SMEM_BYTES = 34688 * 4; // 138752

extern "C" void kernel_launch(void* const* d_in, const int* in_sizes, int n_in,
                              void* d_out, int out_size) {
    const float* x       = (const float*)d_in[0];
    const float* pos     = (const float*)d_in[1];
    const float* w_qkv   = (const float*)d_in[2];
    const float* pos_w1  = (const float*)d_in[3];
    const float* pos_b1  = (const float*)d_in[4];
    const float* pos_w2  = (const float*)d_in[5];
    const float* pos_b2  = (const float*)d_in[6];
    const float* attn_w1 = (const float*)d_in[7];
    const float* attn_b1 = (const float*)d_in[8];
    const float* attn_w2 = (const float*)d_in[9];
    // d_in[10] = attn_b2: constant over j -> cancels in softmax, and only enters sim. Unused.
    float* out = (float*)d_out;

    cudaFuncSetAttribute(pt_main, cudaFuncAttributeMaxDynamicSharedMemorySize, SMEM_BYTES);

    prep_mats<<<193, 256>>>(w_qkv, pos_w2, pos_b2, attn_w1, attn_b1);
    proj_kernel<<<128, 256>>>(x, w_qkv);
    pt_main<<<NB * NSEQ, NT, SMEM_BYTES>>>(pos, pos_w1, pos_b1, pos_w2, pos_b2, attn_w2, out);
}

// round 4
// speedup vs baseline: 1.7151x; 1.7151x over previous
#include <cuda_runtime.h>
#include <cuda_bf16.h>
#include <cstdint>

#define NB    4
#define NSEQ  512
#define DIMK  64
#define NCH   256
#define NT    512

// device scratch
__device__ float d_M   [DIMK * NCH];
__device__ float d_Wq  [DIMK * NCH];
__device__ float d_Wk  [DIMK * NCH];
__device__ float d_cvec[NCH];
__device__ float d_qk1 [NB * NSEQ * NCH];
__device__ float d_kk1 [NB * NSEQ * NCH];
__device__ float d_v   [NB * NSEQ * DIMK];
// B operand (M matrix) bf16 hi/lo, [n][k] rows with XOR-swizzled 16B chunks
__device__ __align__(128) unsigned char d_Bhi[NCH * 128];
__device__ __align__(128) unsigned char d_Blo[NCH * 128];

__device__ __forceinline__ uint32_t smem_to_u32(const void* p) {
    uint32_t a;
    asm("{ .reg .u64 t; cvta.to.shared.u64 t, %1; cvt.u32.u64 %0, t; }" : "=r"(a) : "l"(p));
    return a;
}
__device__ __forceinline__ void ldsm4(uint32_t& r0, uint32_t& r1, uint32_t& r2, uint32_t& r3, uint32_t addr) {
    asm volatile("ldmatrix.sync.aligned.m8n8.x4.shared.b16 {%0,%1,%2,%3}, [%4];"
                 : "=r"(r0), "=r"(r1), "=r"(r2), "=r"(r3) : "r"(addr));
}
__device__ __forceinline__ void mma16816(float* c, const uint32_t* a, uint32_t b0, uint32_t b1) {
    asm volatile("mma.sync.aligned.m16n8k16.row.col.f32.bf16.bf16.f32 "
                 "{%0,%1,%2,%3}, {%4,%5,%6,%7}, {%8,%9}, {%0,%1,%2,%3};"
                 : "+f"(c[0]), "+f"(c[1]), "+f"(c[2]), "+f"(c[3])
                 : "r"(a[0]), "r"(a[1]), "r"(a[2]), "r"(a[3]), "r"(b0), "r"(b1));
}
// swizzled byte offset for element (row, k) in a [row][64] bf16 tile, 128B rows
__device__ __forceinline__ unsigned swz(int row, int k) {
    return row * 128 + ((((k >> 3) ^ (row & 7))) << 4) + (k & 7) * 2;
}

// smem byte layout
#define OFF_BLO  32768
#define OFF_A    65536      // tile t: hi at +t*32768, lo at +t*32768+16384
#define OFF_EXT  196608
#define SMEM_TOTAL 208960
// ext float indices
#define E_QS    0
#define E_W2S   256
#define E_W1S   512
#define E_B1S   704
#define E_PJ    768
#define E_SIMS  1152
#define E_SPART 1664
#define E_GPART 1920
#define E_RPART 2432
#define E_GS    2944
#define E_RED   3008

// -------------------- K0a: fold weights --------------------
__global__ void prep_mats(const float* __restrict__ w_qkv, const float* __restrict__ pos_w2,
                          const float* __restrict__ pos_b2, const float* __restrict__ attn_w1,
                          const float* __restrict__ attn_b1) {
    int c = threadIdx.x, bid = blockIdx.x;
    if (bid == 192) {
        float acc = attn_b1[c];
        #pragma unroll 8
        for (int d = 0; d < DIMK; d++) acc = fmaf(pos_b2[d], attn_w1[d * NCH + c], acc);
        d_cvec[c] = acc;
        return;
    }
    int m = bid >> 6, k = bid & 63;
    const float* src = (m == 0) ? (pos_w2 + k * 64) : (m == 1) ? (w_qkv + k * 192) : (w_qkv + k * 192 + 64);
    float acc = 0.f;
    #pragma unroll 8
    for (int d = 0; d < DIMK; d++) acc = fmaf(src[d], attn_w1[d * NCH + c], acc);
    float* dst = (m == 0) ? d_M : (m == 1) ? d_Wq : d_Wk;
    dst[k * NCH + c] = acc;
}

// -------------------- K0a2: bf16 hi/lo split of M, swizzled [n][k] --------------------
__global__ void prep_msplit() {
    int k = blockIdx.x, n = threadIdx.x;
    float v = d_M[k * NCH + n];
    __nv_bfloat16 h = __float2bfloat16(v);
    __nv_bfloat16 l = __float2bfloat16(v - __bfloat162float(h));
    unsigned sw = swz(n, k);
    *(__nv_bfloat16*)(d_Bhi + sw) = h;
    *(__nv_bfloat16*)(d_Blo + sw) = l;
}

// -------------------- K0b: projections --------------------
__global__ __launch_bounds__(256) void proj_kernel(const float* __restrict__ x,
                                                   const float* __restrict__ w_qkv) {
    __shared__ float xs[16][64];
    int c = threadIdx.x;
    int row0 = blockIdx.x * 16;
    for (int idx = c; idx < 16 * 64; idx += 256) xs[idx >> 6][idx & 63] = x[row0 * 64 + idx];
    __syncthreads();
    float accq[16], acck[16];
    #pragma unroll
    for (int r = 0; r < 16; r++) { accq[r] = 0.f; acck[r] = 0.f; }
    for (int k = 0; k < 64; k++) {
        float wq = d_Wq[k * NCH + c], wk = d_Wk[k * NCH + c];
        #pragma unroll
        for (int r = 0; r < 16; r++) {
            float xv = xs[r][k];
            accq[r] = fmaf(xv, wq, accq[r]);
            acck[r] = fmaf(xv, wk, acck[r]);
        }
    }
    float cv = d_cvec[c];
    #pragma unroll
    for (int r = 0; r < 16; r++) {
        d_qk1[(size_t)(row0 + r) * NCH + c] = accq[r] + cv;
        d_kk1[(size_t)(row0 + r) * NCH + c] = acck[r];
    }
    int d = c & 63, rg = c >> 6;
    for (int r = rg; r < 16; r += 4) {
        float acc = 0.f;
        #pragma unroll 8
        for (int k = 0; k < 64; k++) acc = fmaf(xs[r][k], w_qkv[k * 192 + 128 + d], acc);
        d_v[(size_t)(row0 + r) * 64 + d] = acc;
    }
}

// -------------------- K1: fused attention (warp MMA, bf16 3-term split) --------------------
__global__ __launch_bounds__(NT, 1) void pt_main(const float* __restrict__ pos,
                                                 const float* __restrict__ pos_w1,
                                                 const float* __restrict__ pos_b1,
                                                 const float* __restrict__ pos_w2,
                                                 const float* __restrict__ pos_b2,
                                                 const float* __restrict__ attn_w2,
                                                 float* __restrict__ out) {
    extern __shared__ __align__(1024) char smc[];
    float* ext = (float*)(smc + OFF_EXT);
    float* qs = ext + E_QS; float* w2s = ext + E_W2S; float* w1s = ext + E_W1S;
    float* b1s = ext + E_B1S; float* pj = ext + E_PJ; float* sims = ext + E_SIMS;
    float* spart = ext + E_SPART; float* gpart = ext + E_GPART; float* rpart = ext + E_RPART;
    float* gs = ext + E_GS; float* red = ext + E_RED;

    uint32_t sbase = smem_to_u32(smc);
    int tid = threadIdx.x, wid = tid >> 5, lane = tid & 31;
    int bi = blockIdx.x, b = bi >> 9;

    // stage B hi/lo (64 KB)
    {
        float4* dh = (float4*)smc;
        const float4* sh = (const float4*)d_Bhi;
        for (int idx = tid; idx < 2048; idx += NT) dh[idx] = sh[idx];
        float4* dl = (float4*)(smc + OFF_BLO);
        const float4* sl = (const float4*)d_Blo;
        for (int idx = tid; idx < 2048; idx += NT) dl[idx] = sl[idx];
    }
    if (tid < 256)      { qs[tid] = d_qk1[(size_t)bi * NCH + tid]; w2s[tid] = attn_w2[tid]; }
    else if (tid < 448) { w1s[tid - 256] = pos_w1[tid - 256]; }
    else                { b1s[tid - 448] = pos_b1[tid - 448]; }
    float px = pos[bi * 3 + 0], py = pos[bi * 3 + 1], pz = pos[bi * 3 + 2];
    __syncthreads();

    // warp tiling: mb = m-block (16 rows), nh = n-half (128 cols)
    int mb = wid & 7, nh = wid >> 3;
    int m0 = mb * 16;
    int r8 = lane & 7, g = lane >> 3;
    int rowAoff = (g & 1) << 3, kcA = g >> 1;   // A ldmatrix group mapping
    int nBoff = (g >> 1) << 3, kcB = g & 1;     // B ldmatrix group mapping
    int rq = lane >> 2, t4 = lane & 3;

    // ---------------- PASS 1 ----------------
    for (int t = 0; t < 4; t++) {
        if (tid < 384) {
            int j = tid & 127, d = tid >> 7;
            pj[d * 128 + j] = pos[((size_t)b * NSEQ + t * 128 + j) * 3 + d];
        }
        __syncthreads();
        char* Ah = smc + OFF_A + t * 32768;
        for (int idx = tid; idx < 8192; idx += NT) {
            int j = idx >> 6, k = idx & 63;
            float rx = px - pj[j], ry = py - pj[128 + j], rz = pz - pj[256 + j];
            float v = fmaf(rx, w1s[k], fmaf(ry, w1s[64 + k], fmaf(rz, w1s[128 + k], b1s[k])));
            v = fmaxf(v, 0.f);
            __nv_bfloat16 h = __float2bfloat16(v);
            __nv_bfloat16 l = __float2bfloat16(v - __bfloat162float(h));
            unsigned sw = swz(j, k);
            *(__nv_bfloat16*)(Ah + sw) = h;
            *(__nv_bfloat16*)(Ah + 16384 + sw) = l;
        }
        __syncthreads();

        uint32_t Abase = sbase + OFF_A + t * 32768 + (m0 + rowAoff + r8) * 128;
        float s0 = 0.f, s1 = 0.f;
        const float* kk0 = d_kk1 + ((size_t)((b << 9) + t * 128 + m0 + rq)) * NCH;

        #pragma unroll
        for (int ch = 0; ch < 2; ch++) {
            int n0 = nh * 128 + ch * 64;
            float acc[8][4];
            #pragma unroll
            for (int i = 0; i < 8; i++)
                #pragma unroll
                for (int q = 0; q < 4; q++) acc[i][q] = 0.f;

            #pragma unroll
            for (int ks = 0; ks < 4; ks++) {
                uint32_t ah[4], al[4];
                uint32_t axor = (uint32_t)(((2 * ks + kcA) ^ r8) << 4);
                ldsm4(ah[0], ah[1], ah[2], ah[3], Abase + axor);
                ldsm4(al[0], al[1], al[2], al[3], Abase + 16384 + axor);
                uint32_t bxor = (uint32_t)(((2 * ks + kcB) ^ r8) << 4);
                #pragma unroll
                for (int nb = 0; nb < 4; nb++) {
                    uint32_t baddr = sbase + (n0 + nb * 16 + nBoff + r8) * 128 + bxor;
                    uint32_t bh[4], bl[4];
                    ldsm4(bh[0], bh[1], bh[2], bh[3], baddr);
                    mma16816(acc[2 * nb],     ah, bh[0], bh[1]);
                    mma16816(acc[2 * nb + 1], ah, bh[2], bh[3]);
                    ldsm4(bl[0], bl[1], bl[2], bl[3], baddr + OFF_BLO);
                    mma16816(acc[2 * nb],     al, bh[0], bh[1]);
                    mma16816(acc[2 * nb + 1], al, bh[2], bh[3]);
                    mma16816(acc[2 * nb],     ah, bl[0], bl[1]);
                    mma16816(acc[2 * nb + 1], ah, bl[2], bl[3]);
                }
            }
            // epilogue: rows (m0+rq) and (m0+rq+8), cols n0 + nb8*8 + t4*2 + {0,1}
            #pragma unroll
            for (int nb8 = 0; nb8 < 8; nb8++) {
                int n = n0 + nb8 * 8 + t4 * 2;
                float2 qv = *(const float2*)(qs + n);
                float2 wv = *(const float2*)(w2s + n);
                float2 k0 = *(const float2*)(kk0 + n);
                float2 k1 = *(const float2*)(kk0 + 8 * NCH + n);
                s0 = fmaf(fmaxf(acc[nb8][0] + qv.x - k0.x, 0.f), wv.x,
                     fmaf(fmaxf(acc[nb8][1] + qv.y - k0.y, 0.f), wv.y, s0));
                s1 = fmaf(fmaxf(acc[nb8][2] + qv.x - k1.x, 0.f), wv.x,
                     fmaf(fmaxf(acc[nb8][3] + qv.y - k1.y, 0.f), wv.y, s1));
            }
        }
        // reduce over quad (lanes t4 = 0..3)
        s0 += __shfl_xor_sync(0xffffffffu, s0, 1);
        s0 += __shfl_xor_sync(0xffffffffu, s0, 2);
        s1 += __shfl_xor_sync(0xffffffffu, s1, 1);
        s1 += __shfl_xor_sync(0xffffffffu, s1, 2);
        if (t4 == 0) {
            spart[nh * 128 + m0 + rq] = s0;
            spart[nh * 128 + m0 + rq + 8] = s1;
        }
        __syncthreads();
        if (tid < 128) sims[t * 128 + tid] = spart[tid] + spart[128 + tid];
        __syncthreads();
    }

    // ---------------- softmax over 512 sims ----------------
    {
        float s = sims[tid];
        float m = s;
        #pragma unroll
        for (int off = 16; off; off >>= 1) m = fmaxf(m, __shfl_xor_sync(0xffffffffu, m, off));
        if (lane == 0) red[wid] = m;
        __syncthreads();
        if (tid < 32) {
            float v = (tid < 16) ? red[tid] : -3.4e38f;
            #pragma unroll
            for (int off = 8; off; off >>= 1) v = fmaxf(v, __shfl_xor_sync(0xffffffffu, v, off));
            if (tid == 0) red[32] = v;
        }
        __syncthreads();
        float e = __expf(s - red[32]);
        float tt = e;
        #pragma unroll
        for (int off = 16; off; off >>= 1) tt += __shfl_xor_sync(0xffffffffu, tt, off);
        if (lane == 0) red[wid] = tt;
        __syncthreads();
        if (tid < 32) {
            float v = (tid < 16) ? red[tid] : 0.f;
            #pragma unroll
            for (int off = 8; off; off >>= 1) v += __shfl_xor_sync(0xffffffffu, v, off);
            if (tid == 0) red[33] = v;
        }
        __syncthreads();
        sims[tid] = e / red[33];
        __syncthreads();
    }

    // ---------------- PASS 2: g = a@p (hi+lo from smem), r = a@v ----------------
    {
        int k = tid & 63, jg = tid >> 6;
        float gacc = 0.f, racc = 0.f;
        #pragma unroll 4
        for (int jj = 0; jj < 64; jj++) {
            int j = jg * 64 + jj;
            float a = sims[j];
            int tl = j >> 7, jl = j & 127;
            unsigned sw = swz(jl, k);
            const char* Ah = smc + OFF_A + tl * 32768;
            float ph = __bfloat162float(*(const __nv_bfloat16*)(Ah + sw));
            float pl = __bfloat162float(*(const __nv_bfloat16*)(Ah + 16384 + sw));
            gacc = fmaf(a, ph + pl, gacc);
            racc = fmaf(a, d_v[((size_t)(b << 9) + j) * 64 + k], racc);
        }
        gpart[tid] = gacc;
        rpart[tid] = racc;
        __syncthreads();
        float rsum = 0.f;
        if (tid < 64) {
            float gsum = 0.f;
            #pragma unroll
            for (int w = 0; w < 8; w++) { gsum += gpart[w * 64 + tid]; rsum += rpart[w * 64 + tid]; }
            gs[tid] = gsum;
        }
        __syncthreads();
        if (tid < 64) {
            float o = rsum + pos_b2[tid];
            #pragma unroll 8
            for (int kk = 0; kk < 64; kk++) o = fmaf(gs[kk], pos_w2[kk * 64 + tid], o);
            out[(size_t)bi * 64 + tid] = o;
        }
    }
}

// -------------------- launch --------------------
extern "C" void kernel_launch(void* const* d_in, const int* in_sizes, int n_in,
                              void* d_out, int out_size) {
    const float* x       = (const float*)d_in[0];
    const float* pos     = (const float*)d_in[1];
    const float* w_qkv   = (const float*)d_in[2];
    const float* pos_w1  = (const float*)d_in[3];
    const float* pos_b1  = (const float*)d_in[4];
    const float* pos_w2  = (const float*)d_in[5];
    const float* pos_b2  = (const float*)d_in[6];
    const float* attn_w1 = (const float*)d_in[7];
    const float* attn_b1 = (const float*)d_in[8];
    const float* attn_w2 = (const float*)d_in[9];
    // attn_b2 (d_in[10]) cancels in softmax
    float* out = (float*)d_out;

    cudaFuncSetAttribute(pt_main, cudaFuncAttributeMaxDynamicSharedMemorySize, SMEM_TOTAL);

    prep_mats<<<193, 256>>>(w_qkv, pos_w2, pos_b2, attn_w1, attn_b1);
    prep_msplit<<<64, 256>>>();
    proj_kernel<<<128, 256>>>(x, w_qkv);
    pt_main<<<NB * NSEQ, NT, SMEM_TOTAL>>>(pos, pos_w1, pos_b1, pos_w2, pos_b2, attn_w2, out);
}